// round 8
// baseline (speedup 1.0000x reference)
#include <cuda_runtime.h>
#include <cuda_bf16.h>

#define MAX_NODES 65536

__device__ float g_counts[MAX_NODES];
__device__ int   g_ids_is64;

// ---------------------------------------------------------------------------
// init: block 0 / warp 0 detects id width (int32 data read as int64 fuses two
// random ids -> value outside [0, 2^31) almost surely; 64 probes). All blocks
// zero the sum accumulator (float4, branch-free grid-stride) and counts.
// ---------------------------------------------------------------------------
__global__ void __launch_bounds__(256)
init_kernel(const long long* __restrict__ p64, int n64,
            float4* __restrict__ agg4, int total4, int num_nodes)
{
    if (blockIdx.x == 0 && threadIdx.x < 32) {
        int ok = 1;
        #pragma unroll
        for (int k = 0; k < 2; ++k) {
            long long pos = ((long long)(threadIdx.x * 2 + k) * n64) / 64;
            if (pos < n64) {
                long long v = p64[pos];
                if (v < 0 || v >= (1LL << 31)) ok = 0;
            }
        }
        unsigned m = __ballot_sync(0xFFFFFFFFu, ok);
        if (threadIdx.x == 0) g_ids_is64 = (m == 0xFFFFFFFFu) ? 1 : 0;
    }

    const float4 z = make_float4(0.f, 0.f, 0.f, 0.f);
    int stride = gridDim.x * blockDim.x;
    for (int i = blockIdx.x * blockDim.x + threadIdx.x; i < total4; i += stride)
        agg4[i] = z;
    for (int i = blockIdx.x * blockDim.x + threadIdx.x; i < num_nodes; i += stride)
        g_counts[i] = 0.0f;
}

// ---------------------------------------------------------------------------
// Scatter-add (R6 structure, proven fastest): one warp per FOUR messages.
// Four independent LDG.128 row loads (512B each, coalesced, __ldcs so the
// 512MB message stream doesn't evict the L2-resident 25.6MB sum table), then
// four red.global.add.v4.f32. Lane 0 bumps the four per-node counts.
// ---------------------------------------------------------------------------
__device__ __forceinline__ void red_v4(float* dst, float4 v)
{
    asm volatile("red.global.add.v4.f32 [%0], {%1, %2, %3, %4};"
                 :: "l"(dst), "f"(v.x), "f"(v.y), "f"(v.z), "f"(v.w)
                 : "memory");
}
__device__ __forceinline__ void red_f(float* dst)
{
    asm volatile("red.global.add.f32 [%0], %1;"
                 :: "l"(dst), "f"(1.0f) : "memory");
}

__global__ void __launch_bounds__(256)
scatter_kernel(const void* __restrict__ ids_raw,
               const float* __restrict__ msgs,
               float* __restrict__ sums,
               int num_messages)
{
    int warp = (blockIdx.x * blockDim.x + threadIdx.x) >> 5;
    int lane = threadIdx.x & 31;
    int base = warp << 2;
    if (base >= num_messages) return;
    int is64 = g_ids_is64;

    if (base + 4 <= num_messages) {
        int n0, n1, n2, n3;
        if (is64) {
            const long long* p = (const long long*)ids_raw + base;
            n0 = (int)__ldg(p + 0); n1 = (int)__ldg(p + 1);
            n2 = (int)__ldg(p + 2); n3 = (int)__ldg(p + 3);
        } else {
            const int* p = (const int*)ids_raw + base;
            n0 = __ldg(p + 0); n1 = __ldg(p + 1);
            n2 = __ldg(p + 2); n3 = __ldg(p + 3);
        }
        float4 v0 = __ldcs((const float4*)(msgs + (size_t)(base + 0) * 128) + lane);
        float4 v1 = __ldcs((const float4*)(msgs + (size_t)(base + 1) * 128) + lane);
        float4 v2 = __ldcs((const float4*)(msgs + (size_t)(base + 2) * 128) + lane);
        float4 v3 = __ldcs((const float4*)(msgs + (size_t)(base + 3) * 128) + lane);

        red_v4(sums + (size_t)n0 * 128 + lane * 4, v0);
        red_v4(sums + (size_t)n1 * 128 + lane * 4, v1);
        red_v4(sums + (size_t)n2 * 128 + lane * 4, v2);
        red_v4(sums + (size_t)n3 * 128 + lane * 4, v3);

        if (lane == 0) {
            red_f(&g_counts[n0]); red_f(&g_counts[n1]);
            red_f(&g_counts[n2]); red_f(&g_counts[n3]);
        }
    } else {
        for (int m = base; m < num_messages; ++m) {
            int node = is64 ? (int)((const long long*)ids_raw)[m]
                            : ((const int*)ids_raw)[m];
            float4 v = __ldcs((const float4*)(msgs + (size_t)m * 128) + lane);
            red_v4(sums + (size_t)node * 128 + lane * 4, v);
            if (lane == 0) red_f(&g_counts[node]);
        }
    }
}

// ---------------------------------------------------------------------------
// Finalize: one warp per TWO nodes (two independent count->load->store chains
// per warp, doubles exposed MLP in this latency-bound kernel). Plain stores:
// the output stays L2-resident; next replay's init overwrites it there, so no
// DRAM write stream (the R7 __stcs mistake). Lane 0 writes the arange ids.
// ---------------------------------------------------------------------------
__global__ void __launch_bounds__(256)
finalize_kernel(float* __restrict__ agg, float* __restrict__ ids_out,
                int num_nodes, int write_ids)
{
    int warp  = (blockIdx.x * blockDim.x + threadIdx.x) >> 5;
    int lane  = threadIdx.x & 31;
    int node0 = warp * 2;
    if (node0 >= num_nodes) return;
    int node1 = node0 + 1;
    int has1  = node1 < num_nodes;

    float c0 = __ldg(&g_counts[node0]);
    float c1 = has1 ? __ldg(&g_counts[node1]) : 1.0f;

    float4* row0 = (float4*)(agg + (size_t)node0 * 128) + lane;
    float4* row1 = (float4*)(agg + (size_t)node1 * 128) + lane;
    float4 v0 = *row0;
    float4 v1 = has1 ? *row1 : make_float4(0.f, 0.f, 0.f, 0.f);

    float i0 = 1.0f / fmaxf(c0, 1.0f);
    float i1 = 1.0f / fmaxf(c1, 1.0f);

    v0.x *= i0; v0.y *= i0; v0.z *= i0; v0.w *= i0;
    v1.x *= i1; v1.y *= i1; v1.z *= i1; v1.w *= i1;

    *row0 = v0;
    if (has1) *row1 = v1;

    if (write_ids && lane == 0) {
        ids_out[node0] = (float)node0;
        if (has1) ids_out[node1] = (float)node1;
    }
}

extern "C" void kernel_launch(void* const* d_in, const int* in_sizes, int n_in,
                              void* d_out, int out_size)
{
    const void*  ids  = d_in[0];
    const float* msgs = (const float*)d_in[1];

    const int D = 128;
    int M = in_sizes[1] / D;

    // Output layout: N*129 -> [arange ids | N x 128 agg]; N*128 -> agg only.
    int num_nodes, write_ids;
    if (out_size % 129 == 0) { num_nodes = out_size / 129; write_ids = 1; }
    else                     { num_nodes = out_size / 128; write_ids = 0; }
    if (num_nodes > MAX_NODES) num_nodes = MAX_NODES;

    float* outf    = (float*)d_out;
    float* ids_out = outf;
    float* agg     = write_ids ? (outf + num_nodes) : outf;

    int n64_safe = M / 2;  // valid int64-word count even if data is int32

    {
        int total4 = num_nodes * 32;          // 128 floats = 32 float4 / node
        int blocks = 148 * 8;                 // saturate all SMs, grid-stride
        init_kernel<<<blocks, 256>>>((const long long*)ids, n64_safe,
                                     (float4*)agg, total4, num_nodes);
    }
    {
        int warps  = (M + 3) / 4;             // one warp per 4 messages
        int blocks = (warps * 32 + 255) / 256;
        scatter_kernel<<<blocks, 256>>>(ids, msgs, agg, M);
    }
    {
        int warps  = (num_nodes + 1) / 2;     // one warp per 2 nodes
        int blocks = (warps * 32 + 255) / 256;
        finalize_kernel<<<blocks, 256>>>(agg, ids_out, num_nodes, write_ids);
    }
}

// round 9
// speedup vs baseline: 1.2983x; 1.2983x over previous
#include <cuda_runtime.h>
#include <cuda_bf16.h>

#define MAX_NODES 65536

__device__ float g_counts[MAX_NODES];
__device__ int   g_ids_is64;

// ---------------------------------------------------------------------------
// Detect id width: 64 probes spread over the buffer, one warp. int32 data
// read as int64 fuses two random ids -> value outside [0, 2^31) almost surely.
// ---------------------------------------------------------------------------
__global__ void detect_kernel(const long long* __restrict__ p64, int n64)
{
    int ok = 1;
    #pragma unroll
    for (int k = 0; k < 2; ++k) {
        long long pos = ((long long)(threadIdx.x * 2 + k) * n64) / 64;
        if (pos < n64) {
            long long v = p64[pos];
            if (v < 0 || v >= (1LL << 31)) ok = 0;
        }
    }
    unsigned m = __ballot_sync(0xFFFFFFFFu, ok);
    if (threadIdx.x == 0) g_ids_is64 = (m == 0xFFFFFFFFu) ? 1 : 0;
}

// ---------------------------------------------------------------------------
// Scatter-add (R6 structure, proven fastest — at the REDG issue floor):
// one warp per FOUR messages. Four independent LDG.128 row loads (512B each,
// coalesced, __ldcs so the 512MB message stream doesn't evict the L2-resident
// 25.6MB sum table), then four red.global.add.v4.f32. Lane 0 bumps counts.
// ---------------------------------------------------------------------------
__device__ __forceinline__ void red_v4(float* dst, float4 v)
{
    asm volatile("red.global.add.v4.f32 [%0], {%1, %2, %3, %4};"
                 :: "l"(dst), "f"(v.x), "f"(v.y), "f"(v.z), "f"(v.w)
                 : "memory");
}
__device__ __forceinline__ void red_f(float* dst)
{
    asm volatile("red.global.add.f32 [%0], %1;"
                 :: "l"(dst), "f"(1.0f) : "memory");
}

__global__ void __launch_bounds__(256)
scatter_kernel(const void* __restrict__ ids_raw,
               const float* __restrict__ msgs,
               float* __restrict__ sums,
               int num_messages)
{
    int warp = (blockIdx.x * blockDim.x + threadIdx.x) >> 5;
    int lane = threadIdx.x & 31;
    int base = warp << 2;
    if (base >= num_messages) return;
    int is64 = g_ids_is64;

    if (base + 4 <= num_messages) {
        int n0, n1, n2, n3;
        if (is64) {
            const long long* p = (const long long*)ids_raw + base;
            n0 = (int)__ldg(p + 0); n1 = (int)__ldg(p + 1);
            n2 = (int)__ldg(p + 2); n3 = (int)__ldg(p + 3);
        } else {
            const int* p = (const int*)ids_raw + base;
            n0 = __ldg(p + 0); n1 = __ldg(p + 1);
            n2 = __ldg(p + 2); n3 = __ldg(p + 3);
        }
        float4 v0 = __ldcs((const float4*)(msgs + (size_t)(base + 0) * 128) + lane);
        float4 v1 = __ldcs((const float4*)(msgs + (size_t)(base + 1) * 128) + lane);
        float4 v2 = __ldcs((const float4*)(msgs + (size_t)(base + 2) * 128) + lane);
        float4 v3 = __ldcs((const float4*)(msgs + (size_t)(base + 3) * 128) + lane);

        red_v4(sums + (size_t)n0 * 128 + lane * 4, v0);
        red_v4(sums + (size_t)n1 * 128 + lane * 4, v1);
        red_v4(sums + (size_t)n2 * 128 + lane * 4, v2);
        red_v4(sums + (size_t)n3 * 128 + lane * 4, v3);

        if (lane == 0) {
            red_f(&g_counts[n0]); red_f(&g_counts[n1]);
            red_f(&g_counts[n2]); red_f(&g_counts[n3]);
        }
    } else {
        for (int m = base; m < num_messages; ++m) {
            int node = is64 ? (int)((const long long*)ids_raw)[m]
                            : ((const int*)ids_raw)[m];
            float4 v = __ldcs((const float4*)(msgs + (size_t)m * 128) + lane);
            red_v4(sums + (size_t)node * 128 + lane * 4, v);
            if (lane == 0) red_f(&g_counts[node]);
        }
    }
}

// ---------------------------------------------------------------------------
// Finalize (R6 structure, proven): one warp per node. One uniform count load
// per warp; each lane rescales one float4 of the row. Plain stores so the
// output stays L2-resident across graph replays (the R7 __stcs lesson).
// Lane 0 also writes unique_node_ids = arange (exact in fp32 up to 2^24).
// ---------------------------------------------------------------------------
__global__ void __launch_bounds__(256)
finalize_kernel(float* __restrict__ agg, float* __restrict__ ids_out,
                int num_nodes, int write_ids)
{
    int warp = (blockIdx.x * blockDim.x + threadIdx.x) >> 5;
    int lane = threadIdx.x & 31;
    if (warp >= num_nodes) return;

    float c   = g_counts[warp];                 // uniform per warp
    float inv = 1.0f / fmaxf(c, 1.0f);

    float4* row = (float4*)(agg + (size_t)warp * 128) + lane;
    float4 v = *row;
    v.x *= inv; v.y *= inv; v.z *= inv; v.w *= inv;
    *row = v;

    if (write_ids && lane == 0) ids_out[warp] = (float)warp;
}

extern "C" void kernel_launch(void* const* d_in, const int* in_sizes, int n_in,
                              void* d_out, int out_size)
{
    const void*  ids  = d_in[0];
    const float* msgs = (const float*)d_in[1];

    const int D = 128;
    int M = in_sizes[1] / D;

    // Output layout: N*129 -> [arange ids | N x 128 agg]; N*128 -> agg only.
    int num_nodes, write_ids;
    if (out_size % 129 == 0) { num_nodes = out_size / 129; write_ids = 1; }
    else                     { num_nodes = out_size / 128; write_ids = 0; }
    if (num_nodes > MAX_NODES) num_nodes = MAX_NODES;

    float* outf    = (float*)d_out;
    float* ids_out = outf;
    float* agg     = write_ids ? (outf + num_nodes) : outf;

    int n64_safe = M / 2;  // valid int64-word count even if data is int32

    detect_kernel<<<1, 32>>>((const long long*)ids, n64_safe);

    // Zero the sum accumulator and counts with graph-capturable memset nodes
    // (full write bandwidth, replaces the 7us zero kernel). No allocations.
    cudaMemsetAsync(agg, 0, (size_t)num_nodes * D * sizeof(float), 0);
    {
        void* counts_ptr = nullptr;
        cudaGetSymbolAddress(&counts_ptr, g_counts);
        cudaMemsetAsync(counts_ptr, 0, (size_t)num_nodes * sizeof(float), 0);
    }

    {
        int warps  = (M + 3) / 4;             // one warp per 4 messages
        int blocks = (warps * 32 + 255) / 256;
        scatter_kernel<<<blocks, 256>>>(ids, msgs, agg, M);
    }
    {
        int blocks = (num_nodes * 32 + 255) / 256;
        finalize_kernel<<<blocks, 256>>>(agg, ids_out, num_nodes, write_ids);
    }
}

// round 11
// speedup vs baseline: 1.3247x; 1.0204x over previous
#include <cuda_runtime.h>
#include <cuda_bf16.h>

#define MAX_NODES 65536

__device__ float g_counts[MAX_NODES];

// ---------------------------------------------------------------------------
// Scatter-add: one warp per FOUR messages (proven fastest config; sits at the
// LTS REDG issue floor). Id width (int64 vs int32) is detected INLINE by every
// warp from the same first 32 8-byte words of the id buffer: int32 data read
// as int64 fuses two random ids -> value outside [0, 2^31) unless the high id
// is exactly 0 (p = 1/50000 per word; (1/50000)^32 overall). All warps probe
// identical words -> globally consistent, deterministic. The probe words are
// L1/L2-resident after the first warp, so this costs ~one cached LDG + ballot
// per warp instead of a dedicated 4.9us serial detect launch.
//
// Four independent LDG.128 row loads (512B each, coalesced, __ldcs so the
// 512MB message stream doesn't evict the L2-resident 25.6MB sum table), then
// four red.global.add.v4.f32. Lane 0 bumps the four per-node counts.
// ---------------------------------------------------------------------------
__device__ __forceinline__ void red_v4(float* dst, float4 v)
{
    asm volatile("red.global.add.v4.f32 [%0], {%1, %2, %3, %4};"
                 :: "l"(dst), "f"(v.x), "f"(v.y), "f"(v.z), "f"(v.w)
                 : "memory");
}
__device__ __forceinline__ void red_f(float* dst)
{
    asm volatile("red.global.add.f32 [%0], %1;"
                 :: "l"(dst), "f"(1.0f) : "memory");
}

__global__ void __launch_bounds__(256)
scatter_kernel(const void* __restrict__ ids_raw,
               const float* __restrict__ msgs,
               float* __restrict__ sums,
               int num_messages, int n64)
{
    int warp = (blockIdx.x * blockDim.x + threadIdx.x) >> 5;
    int lane = threadIdx.x & 31;
    int base = warp << 2;
    if (base >= num_messages) return;

    // Inline id-width probe: lane k inspects word k of the first 32 words.
    int ok = 1;
    if (lane < n64) {
        long long v = __ldg((const long long*)ids_raw + lane);
        if (v < 0 || v >= (1LL << 31)) ok = 0;
    }
    int is64 = (__ballot_sync(0xFFFFFFFFu, ok) == 0xFFFFFFFFu);

    if (base + 4 <= num_messages) {
        int n0, n1, n2, n3;
        if (is64) {
            const long long* p = (const long long*)ids_raw + base;
            n0 = (int)__ldg(p + 0); n1 = (int)__ldg(p + 1);
            n2 = (int)__ldg(p + 2); n3 = (int)__ldg(p + 3);
        } else {
            const int* p = (const int*)ids_raw + base;
            n0 = __ldg(p + 0); n1 = __ldg(p + 1);
            n2 = __ldg(p + 2); n3 = __ldg(p + 3);
        }
        float4 v0 = __ldcs((const float4*)(msgs + (size_t)(base + 0) * 128) + lane);
        float4 v1 = __ldcs((const float4*)(msgs + (size_t)(base + 1) * 128) + lane);
        float4 v2 = __ldcs((const float4*)(msgs + (size_t)(base + 2) * 128) + lane);
        float4 v3 = __ldcs((const float4*)(msgs + (size_t)(base + 3) * 128) + lane);

        red_v4(sums + (size_t)n0 * 128 + lane * 4, v0);
        red_v4(sums + (size_t)n1 * 128 + lane * 4, v1);
        red_v4(sums + (size_t)n2 * 128 + lane * 4, v2);
        red_v4(sums + (size_t)n3 * 128 + lane * 4, v3);

        if (lane == 0) {
            red_f(&g_counts[n0]); red_f(&g_counts[n1]);
            red_f(&g_counts[n2]); red_f(&g_counts[n3]);
        }
    } else {
        for (int m = base; m < num_messages; ++m) {
            int node = is64 ? (int)((const long long*)ids_raw)[m]
                            : ((const int*)ids_raw)[m];
            float4 v = __ldcs((const float4*)(msgs + (size_t)m * 128) + lane);
            red_v4(sums + (size_t)node * 128 + lane * 4, v);
            if (lane == 0) red_f(&g_counts[node]);
        }
    }
}

// ---------------------------------------------------------------------------
// Finalize (proven R6 structure): one warp per node. One uniform count load
// per warp; each lane rescales one float4 of the row. Plain stores so the
// output stays L2-resident across graph replays (the R7 __stcs lesson).
// Lane 0 also writes unique_node_ids = arange (exact in fp32 up to 2^24).
// ---------------------------------------------------------------------------
__global__ void __launch_bounds__(256)
finalize_kernel(float* __restrict__ agg, float* __restrict__ ids_out,
                int num_nodes, int write_ids)
{
    int warp = (blockIdx.x * blockDim.x + threadIdx.x) >> 5;
    int lane = threadIdx.x & 31;
    if (warp >= num_nodes) return;

    float c   = g_counts[warp];                 // uniform per warp
    float inv = 1.0f / fmaxf(c, 1.0f);

    float4* row = (float4*)(agg + (size_t)warp * 128) + lane;
    float4 v = *row;
    v.x *= inv; v.y *= inv; v.z *= inv; v.w *= inv;
    *row = v;

    if (write_ids && lane == 0) ids_out[warp] = (float)warp;
}

extern "C" void kernel_launch(void* const* d_in, const int* in_sizes, int n_in,
                              void* d_out, int out_size)
{
    const void*  ids  = d_in[0];
    const float* msgs = (const float*)d_in[1];

    const int D = 128;
    int M = in_sizes[1] / D;

    // Output layout: N*129 -> [arange ids | N x 128 agg]; N*128 -> agg only.
    int num_nodes, write_ids;
    if (out_size % 129 == 0) { num_nodes = out_size / 129; write_ids = 1; }
    else                     { num_nodes = out_size / 128; write_ids = 0; }
    if (num_nodes > MAX_NODES) num_nodes = MAX_NODES;

    float* outf    = (float*)d_out;
    float* ids_out = outf;
    float* agg     = write_ids ? (outf + num_nodes) : outf;

    // Probe width: number of valid 8-byte words even if data is int32,
    // clamped to the 32 words the inline probe inspects.
    int n64_safe = M / 2;
    if (n64_safe > 32) n64_safe = 32;

    // Zero the sum accumulator and counts with graph-capturable memset nodes.
    cudaMemsetAsync(agg, 0, (size_t)num_nodes * D * sizeof(float), 0);
    {
        void* counts_ptr = nullptr;
        cudaGetSymbolAddress(&counts_ptr, g_counts);
        cudaMemsetAsync(counts_ptr, 0, (size_t)num_nodes * sizeof(float), 0);
    }

    {
        int warps  = (M + 3) / 4;             // one warp per 4 messages
        int blocks = (warps * 32 + 255) / 256;
        scatter_kernel<<<blocks, 256>>>(ids, msgs, agg, M, n64_safe);
    }
    {
        int blocks = (num_nodes * 32 + 255) / 256;
        finalize_kernel<<<blocks, 256>>>(agg, ids_out, num_nodes, write_ids);
    }
}

// round 12
// speedup vs baseline: 1.3654x; 1.0307x over previous
#include <cuda_runtime.h>
#include <cuda_bf16.h>

#define MAX_NODES 65536

__device__ int g_counts[MAX_NODES];

// ---------------------------------------------------------------------------
// Inline id-width probe (shared by both kernels): lane k inspects 8-byte word
// k of the id buffer. int32 data read as int64 fuses two random ids -> value
// outside [0, 2^31) unless the high id is exactly 0 (p = 1/50000 per word;
// (1/50000)^32 overall). All warps probe identical words -> globally
// consistent, deterministic; words are L1/L2-resident after the first warp.
// ---------------------------------------------------------------------------
__device__ __forceinline__ int probe_is64(const void* ids_raw, int n64, int lane)
{
    int ok = 1;
    if (lane < n64) {
        long long v = __ldg((const long long*)ids_raw + lane);
        if (v < 0 || v >= (1LL << 31)) ok = 0;
    }
    return (__ballot_sync(0xFFFFFFFFu, ok) == 0xFFFFFFFFu);
}

// ---------------------------------------------------------------------------
// Histogram: count messages per node. Vectorized id loads (int4 = 4 ids for
// int32, two longlong2 = 4 ids for int64) + 4 independent REDG int adds per
// thread per iteration. 20 msgs/node average -> spread-address atomic regime,
// far below LTS serialization. Also writes unique_node_ids = arange.
// ---------------------------------------------------------------------------
__global__ void __launch_bounds__(256)
hist_kernel(const void* __restrict__ ids_raw, int num_messages, int n64,
            float* __restrict__ ids_out, int num_nodes, int write_ids)
{
    int lane = threadIdx.x & 31;
    int is64 = probe_is64(ids_raw, n64, lane);

    int tid    = blockIdx.x * blockDim.x + threadIdx.x;
    int stride = gridDim.x * blockDim.x;

    int quads = num_messages >> 2;      // groups of 4 ids
    if (is64) {
        const longlong2* p = (const longlong2*)ids_raw;
        for (int q = tid; q < quads; q += stride) {
            longlong2 a = __ldg(p + q * 2 + 0);
            longlong2 b = __ldg(p + q * 2 + 1);
            atomicAdd(&g_counts[(int)a.x], 1);
            atomicAdd(&g_counts[(int)a.y], 1);
            atomicAdd(&g_counts[(int)b.x], 1);
            atomicAdd(&g_counts[(int)b.y], 1);
        }
        for (int m = quads * 4 + tid; m < num_messages; m += stride)
            atomicAdd(&g_counts[(int)((const long long*)ids_raw)[m]], 1);
    } else {
        const int4* p = (const int4*)ids_raw;
        for (int q = tid; q < quads; q += stride) {
            int4 a = __ldg(p + q);
            atomicAdd(&g_counts[a.x], 1);
            atomicAdd(&g_counts[a.y], 1);
            atomicAdd(&g_counts[a.z], 1);
            atomicAdd(&g_counts[a.w], 1);
        }
        for (int m = quads * 4 + tid; m < num_messages; m += stride)
            atomicAdd(&g_counts[((const int*)ids_raw)[m]], 1);
    }

    if (write_ids)
        for (int i = tid; i < num_nodes; i += stride)
            ids_out[i] = (float)i;
}

// ---------------------------------------------------------------------------
// Scatter-MEAN: one warp per FOUR messages (proven config, at the REDG issue
// floor). Counts are already final, so each row is scaled by 1/count BEFORE
// the atomic add -> the accumulator IS the mean and no finalize pass (which
// cost 12.2us and a 26MB DRAM round-trip) is needed. Count loads are
// warp-uniform L2-hit broadcasts; __fdividef runs on the idle MUFU pipe.
// Every message's node has count >= 1 by construction. Four independent
// LDG.128 row loads (__ldcs keeps the 512MB stream from evicting the
// L2-resident sum table), then four red.global.add.v4.f32.
// ---------------------------------------------------------------------------
__device__ __forceinline__ void red_v4(float* dst, float4 v)
{
    asm volatile("red.global.add.v4.f32 [%0], {%1, %2, %3, %4};"
                 :: "l"(dst), "f"(v.x), "f"(v.y), "f"(v.z), "f"(v.w)
                 : "memory");
}

__global__ void __launch_bounds__(256)
scatter_kernel(const void* __restrict__ ids_raw,
               const float* __restrict__ msgs,
               float* __restrict__ sums,
               int num_messages, int n64)
{
    int warp = (blockIdx.x * blockDim.x + threadIdx.x) >> 5;
    int lane = threadIdx.x & 31;
    int base = warp << 2;
    if (base >= num_messages) return;

    int is64 = probe_is64(ids_raw, n64, lane);

    if (base + 4 <= num_messages) {
        int n0, n1, n2, n3;
        if (is64) {
            const long long* p = (const long long*)ids_raw + base;
            n0 = (int)__ldg(p + 0); n1 = (int)__ldg(p + 1);
            n2 = (int)__ldg(p + 2); n3 = (int)__ldg(p + 3);
        } else {
            const int* p = (const int*)ids_raw + base;
            n0 = __ldg(p + 0); n1 = __ldg(p + 1);
            n2 = __ldg(p + 2); n3 = __ldg(p + 3);
        }

        float i0 = __fdividef(1.0f, (float)__ldg(&g_counts[n0]));
        float i1 = __fdividef(1.0f, (float)__ldg(&g_counts[n1]));
        float i2 = __fdividef(1.0f, (float)__ldg(&g_counts[n2]));
        float i3 = __fdividef(1.0f, (float)__ldg(&g_counts[n3]));

        float4 v0 = __ldcs((const float4*)(msgs + (size_t)(base + 0) * 128) + lane);
        float4 v1 = __ldcs((const float4*)(msgs + (size_t)(base + 1) * 128) + lane);
        float4 v2 = __ldcs((const float4*)(msgs + (size_t)(base + 2) * 128) + lane);
        float4 v3 = __ldcs((const float4*)(msgs + (size_t)(base + 3) * 128) + lane);

        v0.x *= i0; v0.y *= i0; v0.z *= i0; v0.w *= i0;
        v1.x *= i1; v1.y *= i1; v1.z *= i1; v1.w *= i1;
        v2.x *= i2; v2.y *= i2; v2.z *= i2; v2.w *= i2;
        v3.x *= i3; v3.y *= i3; v3.z *= i3; v3.w *= i3;

        red_v4(sums + (size_t)n0 * 128 + lane * 4, v0);
        red_v4(sums + (size_t)n1 * 128 + lane * 4, v1);
        red_v4(sums + (size_t)n2 * 128 + lane * 4, v2);
        red_v4(sums + (size_t)n3 * 128 + lane * 4, v3);
    } else {
        for (int m = base; m < num_messages; ++m) {
            int node = is64 ? (int)((const long long*)ids_raw)[m]
                            : ((const int*)ids_raw)[m];
            float inv = __fdividef(1.0f, (float)__ldg(&g_counts[node]));
            float4 v = __ldcs((const float4*)(msgs + (size_t)m * 128) + lane);
            v.x *= inv; v.y *= inv; v.z *= inv; v.w *= inv;
            red_v4(sums + (size_t)node * 128 + lane * 4, v);
        }
    }
}

extern "C" void kernel_launch(void* const* d_in, const int* in_sizes, int n_in,
                              void* d_out, int out_size)
{
    const void*  ids  = d_in[0];
    const float* msgs = (const float*)d_in[1];

    const int D = 128;
    int M = in_sizes[1] / D;

    // Output layout: N*129 -> [arange ids | N x 128 agg]; N*128 -> agg only.
    int num_nodes, write_ids;
    if (out_size % 129 == 0) { num_nodes = out_size / 129; write_ids = 1; }
    else                     { num_nodes = out_size / 128; write_ids = 0; }
    if (num_nodes > MAX_NODES) num_nodes = MAX_NODES;

    float* outf    = (float*)d_out;
    float* ids_out = outf;
    float* agg     = write_ids ? (outf + num_nodes) : outf;

    // Probe width: valid 8-byte words even if data is int32, max 32 probed.
    int n64_safe = M / 2;
    if (n64_safe > 32) n64_safe = 32;

    // Zero counts and the output accumulator (graph-capturable memset nodes).
    {
        void* counts_ptr = nullptr;
        cudaGetSymbolAddress(&counts_ptr, g_counts);
        cudaMemsetAsync(counts_ptr, 0, (size_t)num_nodes * sizeof(int), 0);
    }
    cudaMemsetAsync(agg, 0, (size_t)num_nodes * D * sizeof(float), 0);

    // Pass 1: per-node counts (+ arange ids output).
    hist_kernel<<<148 * 8, 256>>>(ids, M, n64_safe, ids_out, num_nodes, write_ids);

    // Pass 2: scatter pre-divided rows -> accumulator is the mean directly.
    {
        int warps  = (M + 3) / 4;             // one warp per 4 messages
        int blocks = (warps * 32 + 255) / 256;
        scatter_kernel<<<blocks, 256>>>(ids, msgs, agg, M, n64_safe);
    }
}